// round 11
// baseline (speedup 1.0000x reference)
#include <cuda_runtime.h>
#include <math.h>

#define Hh 240
#define Ww 1216
#define Bb 4
#define HW (Hh*Ww)
// scalar padded feat buffers, 8-px halo
#define PH2 256
#define PW2 1232
#define PHW2 (PH2*PW2)
// prop tiling: 4 rows x 64 cols per 256-thread block
#define TH 4
#define TW 64
#define SROWS 15
#define SCOLS 76
#define BLK_PER_B 1140   // (240/4)*(1216/64)

// Tap table: one u64 per (pixel, tap), tap-major:
//   bits [0:8)   y0+2  (0..242)
//   bits [8:19)  x0+2  (0..1218)
//   bits [19:31) wy unorm12 (x/4096), [31:43) wx unorm12 (x/4096)
//   bits [43:64) aff, signed fixed-point 2^-18
__device__ unsigned long long g_tab[Bb*9*HW];
// Scalar padded ping-pong feat buffers. Zero-initialized; 8-px border never
// written -> clamped taps read exact zeros.
__device__ float g_fa[Bb*PHW2];
__device__ float g_fb[Bb*PHW2];

__device__ __forceinline__ unsigned long long pack2f(float a, float b){
    float2 t = make_float2(a, b);
    return *reinterpret_cast<unsigned long long*>(&t);
}
__device__ __forceinline__ float2 unpack2f(unsigned long long v){
    return *reinterpret_cast<float2*>(&v);
}

__device__ __forceinline__ float bilin_conf(const float* __restrict__ img, float sy, float sx)
{
    float fy = floorf(sy), fx = floorf(sx);
    float wy = sy - fy,  wx = sx - fx;
    int y0 = (int)fy, x0 = (int)fx;
    int y1 = y0 + 1, x1 = x0 + 1;
    float v00=0.f, v01=0.f, v10=0.f, v11=0.f;
    bool by0 = (unsigned)y0 < Hh, by1 = (unsigned)y1 < Hh;
    bool bx0 = (unsigned)x0 < Ww, bx1 = (unsigned)x1 < Ww;
    if (by0 && bx0) v00 = __ldg(img + y0*Ww + x0);
    if (by0 && bx1) v01 = __ldg(img + y0*Ww + x1);
    if (by1 && bx0) v10 = __ldg(img + y1*Ww + x0);
    if (by1 && bx1) v11 = __ldg(img + y1*Ww + x1);
    return (1.f-wy)*((1.f-wx)*v00 + wx*v01) + wy*((1.f-wx)*v10 + wx*v11);
}

__device__ __forceinline__ void post_pixel(const float acc[24], int b, int y, int xi,
    const float* __restrict__ cb, float iasc,
    float* __restrict__ out_off, float* __restrict__ out_aff)
{
    int pi = y*Ww + xi;

    float offy[9], offx[9];
    #pragma unroll
    for (int m=0;m<9;m++){
        offy[m] = (m<4) ? acc[2*m]   : ((m==4) ? 0.f : acc[2*(m-1)]);
        offx[m] = (m<4) ? acc[2*m+1] : ((m==4) ? 0.f : acc[2*(m-1)+1]);
    }

    float a8[8], ssum = 0.f;
    #pragma unroll
    for (int k=0;k<8;k++){
        float av = tanhf(acc[16+k]) * iasc;
        av *= bilin_conf(cb, (float)y + acc[2*k], (float)xi + acc[2*k+1]);
        a8[k] = av;
        ssum += fabsf(av);
    }
    float s = ssum + 1e-4f;
    if (s < 1.f) s = 1.f;
    float inv = 1.0f / s;
    float asum = 0.f;
    #pragma unroll
    for (int k=0;k<8;k++){ a8[k] *= inv; asum += a8[k]; }
    float aref = 1.f - asum;

    float affv[9];
    #pragma unroll
    for (int m=0;m<9;m++) affv[m] = (m<4) ? a8[m] : ((m==4) ? aref : a8[m-1]);

    // plain stores (measured: __stcs here cost +70us)
    #pragma unroll
    for (int m=0;m<9;m++){
        out_off[((size_t)b*18 + 2*m    )*HW + pi] = offy[m];
        out_off[((size_t)b*18 + 2*m + 1)*HW + pi] = offx[m];
        out_aff[((size_t)b*9  + m      )*HW + pi] = affv[m];
    }

    // encode tap table
    #pragma unroll
    for (int m=0;m<9;m++){
        float ty = (float)(y  + m/3 - 1) + offy[m];
        float tx = (float)(xi + m%3 - 1) + offx[m];
        float fy = floorf(ty), fx2 = floorf(tx);
        float wy = ty - fy, wx = tx - fx2;
        int y0 = (int)fy, x0 = (int)fx2;
        if (y0 < -2) y0 = -2;  if (y0 > Hh) y0 = Hh;   // clamp keeps invalidity
        if (x0 < -2) x0 = -2;  if (x0 > Ww) x0 = Ww;
        unsigned yq = (unsigned)(y0 + 2);              // 0..242, 8 bits
        unsigned xq = (unsigned)(x0 + 2);              // 0..1218, 11 bits
        unsigned uy = __float2uint_rn(wy * 4096.f); if (uy > 4095u) uy = 4095u;
        unsigned ux = __float2uint_rn(wx * 4096.f); if (ux > 4095u) ux = 4095u;
        int ia = __float2int_rn(affv[m] * 262144.f);
        unsigned long long v =
              ((unsigned long long)((unsigned)ia & 0x1FFFFFu) << 43)
            | ((unsigned long long)ux << 31)
            | ((unsigned long long)uy << 19)
            | ((unsigned long long)xq << 8)
            | (unsigned long long)yq;
        g_tab[(b*9 + m)*HW + pi] = v;
    }
}

// Fused: 3x3 conv (8ch -> 24ch, f32x2 over a 2-pixel pair) + post + init feat.
__global__ void __launch_bounds__(256) conv_post_kernel(
    const float* __restrict__ feat_init,
    const float* __restrict__ guidance,
    const float* __restrict__ confidence,
    const float* __restrict__ feat_fix,
    const float* __restrict__ w_oa,
    const float* __restrict__ b_oa,
    const float* __restrict__ ascale,
    float* __restrict__ out)
{
    __shared__ unsigned long long wsh2[1728];   // (w,w) pairs, layout [c][dy][dx][o]
    for (int j = threadIdx.x; j < 1728; j += 256){
        int o = j % 24, r = j / 24;
        float w = __ldg(w_oa + o*72 + r);
        wsh2[j] = pack2f(w, w);
    }
    __syncthreads();

    int t  = blockIdx.x*256 + threadIdx.x;
    int pp = t*2;
    int b  = pp / HW;
    int p  = pp - b*HW;
    int y  = p / Ww;
    int x  = p - y*Ww;                 // pixels (x, x+1), x even

    unsigned long long accp[24];
    #pragma unroll
    for (int o=0;o<24;o++){ float bo = __ldg(b_oa+o); accp[o] = pack2f(bo, bo); }

    const float* gb = guidance + (size_t)b*8*HW;
    #pragma unroll 1
    for (int c=0;c<8;c++){
        #pragma unroll
        for (int dy=0;dy<3;dy++){
            int yy = y + dy - 1;
            if ((unsigned)yy >= Hh) continue;
            const float* grow = gb + c*HW + yy*Ww;
            float gva[4];
            gva[0] = (x >= 1)     ? __ldg(grow + x - 1) : 0.f;
            gva[1] =                __ldg(grow + x);
            gva[2] =                __ldg(grow + x + 1);
            gva[3] = (x + 2 < Ww) ? __ldg(grow + x + 2) : 0.f;
            #pragma unroll
            for (int dx=0;dx<3;dx++){
                unsigned long long ga = pack2f(gva[dx], gva[dx+1]);
                const ulonglong2* wp = (const ulonglong2*)(wsh2 + (c*9 + dy*3 + dx)*24);
                #pragma unroll
                for (int q=0;q<12;q++){
                    ulonglong2 w2 = wp[q];
                    asm("fma.rn.f32x2 %0, %1, %2, %0;" : "+l"(accp[2*q])   : "l"(ga), "l"(w2.x));
                    asm("fma.rn.f32x2 %0, %1, %2, %0;" : "+l"(accp[2*q+1]) : "l"(ga), "l"(w2.y));
                }
            }
        }
    }

    float acc0[24], acc1[24];
    #pragma unroll
    for (int o=0;o<24;o++){ float2 u = unpack2f(accp[o]); acc0[o]=u.x; acc1[o]=u.y; }

    const float* cb  = confidence + (size_t)b*HW;
    const float* fxb = feat_fix   + (size_t)b*HW;
    const float* fib = feat_init  + (size_t)b*HW;
    float iasc = 1.0f / (__ldg(ascale) + 1e-8f);

    float* out_off = out + (size_t)Bb*HW;
    float* out_aff = out + (size_t)Bb*HW*19;

    post_pixel(acc0, b, y, x,   cb, iasc, out_off, out_aff);
    post_pixel(acc1, b, y, x+1, cb, iasc, out_off, out_aff);

    // pre-blended initial feat into scalar padded buffer
    float fv0 = __ldg(fxb + p),     fi0 = __ldg(fib + p);
    float fv1 = __ldg(fxb + p + 1), fi1 = __ldg(fib + p + 1);
    float f0 = (fv0 > 0.f) ? fv0 : fi0;
    float f1 = (fv1 > 0.f) ? fv1 : fi1;
    float* pa = g_fa + (size_t)b*PHW2 + (y+8)*PW2 + (x+8);
    pa[0] = f0;
    pa[1] = f1;
}

// One propagation iteration. Block = 4x64 tile; pair-format feat window in smem.
__global__ void __launch_bounds__(256) prop_kernel(
    const float* __restrict__ feat_fix, float* __restrict__ dout, int it)
{
    __shared__ float2 sf2[SROWS*SCOLS];   // pairs: sf2[r*76+c] = (f[c], f[c+1]); 9.1KB

    int bid = blockIdx.x;
    int tid = threadIdx.x;
    int b   = bid / BLK_PER_B;
    int r   = bid - b*BLK_PER_B;
    int yt  = (r / 19) * TH;
    int xs  = (r - (r/19)*19) * TW;

    const float* fin = ((it & 1) ? g_fb : g_fa) + (size_t)b*PHW2;

    // Stage pair window: padded rows [yt+3, yt+17], cols [xs, xs+76].
    // src is 16B-aligned (xs % 64 == 0, PW2 % 4 == 0).
    {
        const float* src = fin + (yt+3)*PW2 + xs;
        #pragma unroll
        for (int pass=0; pass<2; pass++){
            int j = pass*256 + tid;           // 285 float4 jobs (15 rows x 19)
            if (j < SROWS*19){
                int rr = j / 19, qq = j - rr*19;
                const float* sp = src + rr*PW2 + qq*4;
                float4 q4 = *reinterpret_cast<const float4*>(sp);
                float nx = sp[4];
                float2* d = sf2 + rr*SCOLS + qq*4;
                d[0] = make_float2(q4.x, q4.y);
                d[1] = make_float2(q4.y, q4.z);
                d[2] = make_float2(q4.z, q4.w);
                d[3] = make_float2(q4.w, nx);
            }
        }
        __syncthreads();
    }

    int dy = tid >> 6, dx = tid & 63;
    int y  = yt + dy, x = xs + dx;
    int p  = y*Ww + x;
    int ybase = yt - 3;   // sr = yq - ybase
    int xbase = xs - 6;   // sc = xq - xbase

    float acc = 0.f;
    #pragma unroll
    for (int k=0;k<9;k++){
        unsigned long long v = __ldg(&g_tab[(b*9 + k)*HW + p]);
        unsigned t8  = (unsigned)(v >> 8);
        unsigned t20 = (unsigned)(v >> 20);
        // mantissa-injection decode: w = 1.w_bits - 1.0
        float wy = __uint_as_float(0x3F800000u | (t8  & 0x7FF800u)) - 1.0f;
        float wx = __uint_as_float(0x3F800000u | (t20 & 0x7FF800u)) - 1.0f;
        int yq = (int)((unsigned)v & 0xFFu);
        int xq = (int)(t8 & 0x7FFu);
        float iaf = (float)(int)((long long)v >> 43);   // aff * 2^18

        int sr = yq - ybase;
        int sc = xq - xbase;
        float2 c0, c1;
        if ((unsigned)sr <= 13u && (unsigned)sc <= 74u){
            int si = sr*SCOLS + sc;
            c0 = sf2[si];
            c1 = sf2[si + SCOLS];
        } else {
            // rare out-of-window tap: exact global fallback (always in-bounds)
            const float* g = fin + (yq + 6)*PW2 + (xq + 6);
            c0 = make_float2(__ldg(g),       __ldg(g + 1));
            c1 = make_float2(__ldg(g + PW2), __ldg(g + PW2 + 1));
        }
        float top = c0.x + wx*(c0.y - c0.x);
        float bot = c1.x + wx*(c1.y - c1.x);
        acc = fmaf(iaf, top + wy*(bot - top), acc);
    }
    acc *= (1.f/262144.f);   // deferred aff fixed-point scale

    int tg = b*HW + p;
    if (it != 17){
        float fv = __ldg(feat_fix + tg);
        float f  = (fv > 0.f) ? fv : acc;
        float* fout = ((it & 1) ? g_fa : g_fb) + (size_t)b*PHW2;
        fout[(y+8)*PW2 + (x+8)] = f;
    } else {
        dout[tg] = acc;                       // final: raw aggregate
    }
}

extern "C" void kernel_launch(void* const* d_in, const int* in_sizes, int n_in,
                              void* d_out, int out_size)
{
    const float* feat_init  = (const float*)d_in[0];
    const float* guidance   = (const float*)d_in[1];
    const float* confidence = (const float*)d_in[2];
    const float* feat_fix   = (const float*)d_in[3];
    const float* w_oa       = (const float*)d_in[4];
    const float* b_oa       = (const float*)d_in[5];
    const float* ascale     = (const float*)d_in[6];
    float* out = (float*)d_out;

    (void)in_sizes; (void)n_in; (void)out_size;

    conv_post_kernel<<<(Bb*HW/2)/256, 256>>>(feat_init, guidance, confidence,
                                             feat_fix, w_oa, b_oa, ascale, out);
    for (int it = 0; it < 18; ++it)
        prop_kernel<<<Bb*BLK_PER_B, 256>>>(feat_fix, out, it);
}

// round 14
// speedup vs baseline: 1.0985x; 1.0985x over previous
#include <cuda_runtime.h>
#include <math.h>

#define Hh 240
#define Ww 1216
#define Bb 4
#define HW (Hh*Ww)
// scalar padded feat buffers, 8-px halo
#define PH2 256
#define PW2 1232
#define PHW2 (PH2*PW2)
// prop tiling: 4 rows x 64 cols per 256-thread block
#define TH 4
#define TW 64
#define SROWS 15
#define SCOLS 76
#define BLK_PER_B 1140   // (240/4)*(1216/64)

// Tap table: one u64 per (pixel, tap), tap-major:
//   bits [0:8)   y0+2  (0..242)
//   bits [8:19)  x0+2  (0..1218)
//   bits [19:31) wy unorm12 (x/4096), [31:43) wx unorm12 (x/4096)
//   bits [43:64) aff, signed fixed-point 2^-18
__device__ unsigned long long g_tab[Bb*9*HW];
// Scalar padded ping-pong feat buffers. Zero-initialized; 8-px border never
// written -> clamped taps read exact zeros.
__device__ float g_fa[Bb*PHW2];
__device__ float g_fb[Bb*PHW2];

__device__ __forceinline__ unsigned long long pack2f(float a, float b){
    float2 t = make_float2(a, b);
    return *reinterpret_cast<unsigned long long*>(&t);
}
__device__ __forceinline__ float2 unpack2f(unsigned long long v){
    return *reinterpret_cast<float2*>(&v);
}

__device__ __forceinline__ float bilin_conf(const float* __restrict__ img, float sy, float sx)
{
    float fy = floorf(sy), fx = floorf(sx);
    float wy = sy - fy,  wx = sx - fx;
    int y0 = (int)fy, x0 = (int)fx;
    int y1 = y0 + 1, x1 = x0 + 1;
    float v00=0.f, v01=0.f, v10=0.f, v11=0.f;
    bool by0 = (unsigned)y0 < Hh, by1 = (unsigned)y1 < Hh;
    bool bx0 = (unsigned)x0 < Ww, bx1 = (unsigned)x1 < Ww;
    if (by0 && bx0) v00 = __ldg(img + y0*Ww + x0);
    if (by0 && bx1) v01 = __ldg(img + y0*Ww + x1);
    if (by1 && bx0) v10 = __ldg(img + y1*Ww + x0);
    if (by1 && bx1) v11 = __ldg(img + y1*Ww + x1);
    return (1.f-wy)*((1.f-wx)*v00 + wx*v01) + wy*((1.f-wx)*v10 + wx*v11);
}

__device__ __forceinline__ void post_pixel(const float acc[24], int b, int y, int xi,
    const float* __restrict__ cb, float iasc,
    float* __restrict__ out_off, float* __restrict__ out_aff)
{
    int pi = y*Ww + xi;

    float offy[9], offx[9];
    #pragma unroll
    for (int m=0;m<9;m++){
        offy[m] = (m<4) ? acc[2*m]   : ((m==4) ? 0.f : acc[2*(m-1)]);
        offx[m] = (m<4) ? acc[2*m+1] : ((m==4) ? 0.f : acc[2*(m-1)+1]);
    }

    float a8[8], ssum = 0.f;
    #pragma unroll
    for (int k=0;k<8;k++){
        float av = tanhf(acc[16+k]) * iasc;
        av *= bilin_conf(cb, (float)y + acc[2*k], (float)xi + acc[2*k+1]);
        a8[k] = av;
        ssum += fabsf(av);
    }
    float s = ssum + 1e-4f;
    if (s < 1.f) s = 1.f;
    float inv = 1.0f / s;
    float asum = 0.f;
    #pragma unroll
    for (int k=0;k<8;k++){ a8[k] *= inv; asum += a8[k]; }
    float aref = 1.f - asum;

    float affv[9];
    #pragma unroll
    for (int m=0;m<9;m++) affv[m] = (m<4) ? a8[m] : ((m==4) ? aref : a8[m-1]);

    // plain stores (measured: __stcs here cost +70us)
    #pragma unroll
    for (int m=0;m<9;m++){
        out_off[((size_t)b*18 + 2*m    )*HW + pi] = offy[m];
        out_off[((size_t)b*18 + 2*m + 1)*HW + pi] = offx[m];
        out_aff[((size_t)b*9  + m      )*HW + pi] = affv[m];
    }

    // encode tap table
    #pragma unroll
    for (int m=0;m<9;m++){
        float ty = (float)(y  + m/3 - 1) + offy[m];
        float tx = (float)(xi + m%3 - 1) + offx[m];
        float fy = floorf(ty), fx2 = floorf(tx);
        float wy = ty - fy, wx = tx - fx2;
        int y0 = (int)fy, x0 = (int)fx2;
        if (y0 < -2) y0 = -2;  if (y0 > Hh) y0 = Hh;   // clamp keeps invalidity
        if (x0 < -2) x0 = -2;  if (x0 > Ww) x0 = Ww;
        unsigned yq = (unsigned)(y0 + 2);              // 0..242, 8 bits
        unsigned xq = (unsigned)(x0 + 2);              // 0..1218, 11 bits
        unsigned uy = __float2uint_rn(wy * 4096.f); if (uy > 4095u) uy = 4095u;
        unsigned ux = __float2uint_rn(wx * 4096.f); if (ux > 4095u) ux = 4095u;
        int ia = __float2int_rn(affv[m] * 262144.f);
        unsigned long long v =
              ((unsigned long long)((unsigned)ia & 0x1FFFFFu) << 43)
            | ((unsigned long long)ux << 31)
            | ((unsigned long long)uy << 19)
            | ((unsigned long long)xq << 8)
            | (unsigned long long)yq;
        g_tab[(b*9 + m)*HW + pi] = v;
    }
}

// Fused: 3x3 conv (8ch -> 24ch, f32x2 over a 2-pixel pair) + post + init feat.
__global__ void __launch_bounds__(256) conv_post_kernel(
    const float* __restrict__ feat_init,
    const float* __restrict__ guidance,
    const float* __restrict__ confidence,
    const float* __restrict__ feat_fix,
    const float* __restrict__ w_oa,
    const float* __restrict__ b_oa,
    const float* __restrict__ ascale,
    float* __restrict__ out)
{
    __shared__ unsigned long long wsh2[1728];   // (w,w) pairs, layout [c][dy][dx][o]
    for (int j = threadIdx.x; j < 1728; j += 256){
        int o = j % 24, r = j / 24;
        float w = __ldg(w_oa + o*72 + r);
        wsh2[j] = pack2f(w, w);
    }
    __syncthreads();

    int t  = blockIdx.x*256 + threadIdx.x;
    int pp = t*2;
    int b  = pp / HW;
    int p  = pp - b*HW;
    int y  = p / Ww;
    int x  = p - y*Ww;                 // pixels (x, x+1), x even

    unsigned long long accp[24];
    #pragma unroll
    for (int o=0;o<24;o++){ float bo = __ldg(b_oa+o); accp[o] = pack2f(bo, bo); }

    const float* gb = guidance + (size_t)b*8*HW;
    #pragma unroll 1
    for (int c=0;c<8;c++){
        #pragma unroll
        for (int dy=0;dy<3;dy++){
            int yy = y + dy - 1;
            if ((unsigned)yy >= Hh) continue;
            const float* grow = gb + c*HW + yy*Ww;
            float gva[4];
            gva[0] = (x >= 1)     ? __ldg(grow + x - 1) : 0.f;
            gva[1] =                __ldg(grow + x);
            gva[2] =                __ldg(grow + x + 1);
            gva[3] = (x + 2 < Ww) ? __ldg(grow + x + 2) : 0.f;
            #pragma unroll
            for (int dx=0;dx<3;dx++){
                unsigned long long ga = pack2f(gva[dx], gva[dx+1]);
                const ulonglong2* wp = (const ulonglong2*)(wsh2 + (c*9 + dy*3 + dx)*24);
                #pragma unroll
                for (int q=0;q<12;q++){
                    ulonglong2 w2 = wp[q];
                    asm("fma.rn.f32x2 %0, %1, %2, %0;" : "+l"(accp[2*q])   : "l"(ga), "l"(w2.x));
                    asm("fma.rn.f32x2 %0, %1, %2, %0;" : "+l"(accp[2*q+1]) : "l"(ga), "l"(w2.y));
                }
            }
        }
    }

    float acc0[24], acc1[24];
    #pragma unroll
    for (int o=0;o<24;o++){ float2 u = unpack2f(accp[o]); acc0[o]=u.x; acc1[o]=u.y; }

    const float* cb  = confidence + (size_t)b*HW;
    const float* fxb = feat_fix   + (size_t)b*HW;
    const float* fib = feat_init  + (size_t)b*HW;
    float iasc = 1.0f / (__ldg(ascale) + 1e-8f);

    float* out_off = out + (size_t)Bb*HW;
    float* out_aff = out + (size_t)Bb*HW*19;

    post_pixel(acc0, b, y, x,   cb, iasc, out_off, out_aff);
    post_pixel(acc1, b, y, x+1, cb, iasc, out_off, out_aff);

    // pre-blended initial feat into scalar padded buffer
    float fv0 = __ldg(fxb + p),     fi0 = __ldg(fib + p);
    float fv1 = __ldg(fxb + p + 1), fi1 = __ldg(fib + p + 1);
    float f0 = (fv0 > 0.f) ? fv0 : fi0;
    float f1 = (fv1 > 0.f) ? fv1 : fi1;
    float* pa = g_fa + (size_t)b*PHW2 + (y+8)*PW2 + (x+8);
    pa[0] = f0;
    pa[1] = f1;
}

// One propagation iteration. Block = 4x64 tile; scalar feat window in smem
// (4.6KB -> 8 blocks/SM). Decode path trimmed: mantissa-injection weights,
// deferred aff scale, folded window index.
__global__ void __launch_bounds__(256) prop_kernel(
    const float* __restrict__ feat_fix, float* __restrict__ dout, int it)
{
    __shared__ float sf[SROWS*SCOLS];   // 15 x 76 floats = 4560 B

    int bid = blockIdx.x;
    int tid = threadIdx.x;
    int b   = bid / BLK_PER_B;
    int r   = bid - b*BLK_PER_B;
    int yt  = (r / 19) * TH;
    int xs  = (r - (r/19)*19) * TW;

    const float* fin = ((it & 1) ? g_fb : g_fa) + (size_t)b*PHW2;

    // Stage feat window: padded rows [yt+3, yt+17], cols [xs+2, xs+77].
    // Source is 8B-aligned -> float2 staging (570 jobs).
    {
        const float* src = fin + (yt+3)*PW2 + (xs+2);
        #pragma unroll
        for (int pass=0; pass<3; pass++){
            int j = pass*256 + tid;
            if (j < SROWS*38){
                int rr = j / 38, cc = j - rr*38;
                float2 v2 = *reinterpret_cast<const float2*>(src + rr*PW2 + cc*2);
                sf[rr*SCOLS + cc*2]     = v2.x;
                sf[rr*SCOLS + cc*2 + 1] = v2.y;
            }
        }
        __syncthreads();
    }

    int dy = tid >> 6, dx = tid & 63;
    int y  = yt + dy, x = xs + dx;
    int p  = y*Ww + x;
    // padded tap coords are (yq+6, xq+6); window origin is (yt+3, xs+2):
    //   sr = (yq+6)-(yt+3) = yq - (yt-3)   -> ybase = yt-3
    //   sc = (xq+6)-(xs+2) = xq - (xs-4)   -> xbase = xs-4
    int ybase = yt - 3;
    int xbase = xs - 4;
    int sioff = ybase*SCOLS + xbase;         // si = yq*76 + xq - sioff

    float acc = 0.f;
    #pragma unroll
    for (int k=0;k<9;k++){
        unsigned long long v = __ldg(&g_tab[(b*9 + k)*HW + p]);
        unsigned lo  = (unsigned)v;
        unsigned t8  = lo >> 8;                 // wy field + xq live in low word
        unsigned t20 = (unsigned)(v >> 20);     // 64-bit shift: wx spans bits 31..42
        // mantissa-injection decode: w = (1.0 | frac_bits) - 1.0
        float wy = __uint_as_float(0x3F800000u | (t8  & 0x7FF800u)) - 1.0f;
        float wx = __uint_as_float(0x3F800000u | (t20 & 0x7FF800u)) - 1.0f;
        int yq = (int)(lo & 0xFFu);
        int xq = (int)(t8 & 0x7FFu);
        float iaf = (float)(int)((long long)v >> 43);   // aff * 2^18

        float v00, v01, v10, v11;
        if ((unsigned)(yq - ybase) <= 13u && (unsigned)(xq - xbase) <= 74u){
            int si = yq*SCOLS + xq - sioff;
            v00 = sf[si];
            v01 = sf[si + 1];
            v10 = sf[si + SCOLS];
            v11 = sf[si + SCOLS + 1];
        } else {
            // rare out-of-window tap: exact global fallback (always in-bounds)
            const float* g = fin + (yq + 6)*PW2 + (xq + 6);
            v00 = __ldg(g);
            v01 = __ldg(g + 1);
            v10 = __ldg(g + PW2);
            v11 = __ldg(g + PW2 + 1);
        }
        float top = v00 + wx*(v01 - v00);
        float bot = v10 + wx*(v11 - v10);
        acc = fmaf(iaf, top + wy*(bot - top), acc);
    }
    acc *= (1.f/262144.f);   // deferred aff fixed-point scale

    int tg = b*HW + p;
    if (it != 17){
        float fv = __ldg(feat_fix + tg);
        float f  = (fv > 0.f) ? fv : acc;
        float* fout = ((it & 1) ? g_fa : g_fb) + (size_t)b*PHW2;
        fout[(y+8)*PW2 + (x+8)] = f;
    } else {
        dout[tg] = acc;                       // final: raw aggregate
    }
}

extern "C" void kernel_launch(void* const* d_in, const int* in_sizes, int n_in,
                              void* d_out, int out_size)
{
    const float* feat_init  = (const float*)d_in[0];
    const float* guidance   = (const float*)d_in[1];
    const float* confidence = (const float*)d_in[2];
    const float* feat_fix   = (const float*)d_in[3];
    const float* w_oa       = (const float*)d_in[4];
    const float* b_oa       = (const float*)d_in[5];
    const float* ascale     = (const float*)d_in[6];
    float* out = (float*)d_out;

    (void)in_sizes; (void)n_in; (void)out_size;

    conv_post_kernel<<<(Bb*HW/2)/256, 256>>>(feat_init, guidance, confidence,
                                             feat_fix, w_oa, b_oa, ascale, out);
    for (int it = 0; it < 18; ++it)
        prop_kernel<<<Bb*BLK_PER_B, 256>>>(feat_fix, out, it);
}

// round 15
// speedup vs baseline: 1.1719x; 1.0668x over previous
#include <cuda_runtime.h>
#include <math.h>

#define Hh 240
#define Ww 1216
#define Bb 4
#define HW (Hh*Ww)
// scalar padded feat buffers, 8-px halo
#define PH2 256
#define PW2 1232
#define PHW2 (PH2*PW2)
// prop tiling: 4 rows x 64 cols per 256-thread block
#define TH 4
#define TW 64
#define SROWS 15
#define SCOLS 76
#define BLK_PER_B 1140   // (240/4)*(1216/64)

// Tap table: one u64 per (pixel, tap), tap-major, 8 taps (center tap m=4 is
// implicit: zero offset, weight aff_ref = 1 - sum(others)):
//   bits [0:8)   y0+2  (0..242)
//   bits [8:19)  x0+2  (0..1218)
//   bits [19:31) wy unorm12 (x/4096), [31:43) wx unorm12 (x/4096)
//   bits [43:64) aff, signed fixed-point 2^-18
__device__ unsigned long long g_tab[Bb*8*HW];
// Scalar padded ping-pong feat buffers. Zero-initialized; 8-px border never
// written -> clamped taps read exact zeros.
__device__ float g_fa[Bb*PHW2];
__device__ float g_fb[Bb*PHW2];

__device__ __forceinline__ unsigned long long pack2f(float a, float b){
    float2 t = make_float2(a, b);
    return *reinterpret_cast<unsigned long long*>(&t);
}
__device__ __forceinline__ float2 unpack2f(unsigned long long v){
    return *reinterpret_cast<float2*>(&v);
}

__device__ __forceinline__ float bilin_conf(const float* __restrict__ img, float sy, float sx)
{
    float fy = floorf(sy), fx = floorf(sx);
    float wy = sy - fy,  wx = sx - fx;
    int y0 = (int)fy, x0 = (int)fx;
    int y1 = y0 + 1, x1 = x0 + 1;
    float v00=0.f, v01=0.f, v10=0.f, v11=0.f;
    bool by0 = (unsigned)y0 < Hh, by1 = (unsigned)y1 < Hh;
    bool bx0 = (unsigned)x0 < Ww, bx1 = (unsigned)x1 < Ww;
    if (by0 && bx0) v00 = __ldg(img + y0*Ww + x0);
    if (by0 && bx1) v01 = __ldg(img + y0*Ww + x1);
    if (by1 && bx0) v10 = __ldg(img + y1*Ww + x0);
    if (by1 && bx1) v11 = __ldg(img + y1*Ww + x1);
    return (1.f-wy)*((1.f-wx)*v00 + wx*v01) + wy*((1.f-wx)*v10 + wx*v11);
}

__device__ __forceinline__ void post_pixel(const float acc[24], int b, int y, int xi,
    const float* __restrict__ cb, float iasc,
    float* __restrict__ out_off, float* __restrict__ out_aff)
{
    int pi = y*Ww + xi;

    float offy[9], offx[9];
    #pragma unroll
    for (int m=0;m<9;m++){
        offy[m] = (m<4) ? acc[2*m]   : ((m==4) ? 0.f : acc[2*(m-1)]);
        offx[m] = (m<4) ? acc[2*m+1] : ((m==4) ? 0.f : acc[2*(m-1)+1]);
    }

    float a8[8], ssum = 0.f;
    #pragma unroll
    for (int k=0;k<8;k++){
        float av = tanhf(acc[16+k]) * iasc;
        av *= bilin_conf(cb, (float)y + acc[2*k], (float)xi + acc[2*k+1]);
        a8[k] = av;
        ssum += fabsf(av);
    }
    float s = ssum + 1e-4f;
    if (s < 1.f) s = 1.f;
    float inv = 1.0f / s;
    float asum = 0.f;
    #pragma unroll
    for (int k=0;k<8;k++){ a8[k] *= inv; asum += a8[k]; }
    float aref = 1.f - asum;

    float affv[9];
    #pragma unroll
    for (int m=0;m<9;m++) affv[m] = (m<4) ? a8[m] : ((m==4) ? aref : a8[m-1]);

    // plain stores (measured: __stcs here cost +70us)
    #pragma unroll
    for (int m=0;m<9;m++){
        out_off[((size_t)b*18 + 2*m    )*HW + pi] = offy[m];
        out_off[((size_t)b*18 + 2*m + 1)*HW + pi] = offx[m];
        out_aff[((size_t)b*9  + m      )*HW + pi] = affv[m];
    }

    // encode tap table: 8 entries, center tap (m=4) implicit in prop
    #pragma unroll
    for (int m=0;m<9;m++){
        if (m == 4) continue;
        int slot = (m < 4) ? m : m - 1;
        float ty = (float)(y  + m/3 - 1) + offy[m];
        float tx = (float)(xi + m%3 - 1) + offx[m];
        float fy = floorf(ty), fx2 = floorf(tx);
        float wy = ty - fy, wx = tx - fx2;
        int y0 = (int)fy, x0 = (int)fx2;
        if (y0 < -2) y0 = -2;  if (y0 > Hh) y0 = Hh;   // clamp keeps invalidity
        if (x0 < -2) x0 = -2;  if (x0 > Ww) x0 = Ww;
        unsigned yq = (unsigned)(y0 + 2);              // 0..242, 8 bits
        unsigned xq = (unsigned)(x0 + 2);              // 0..1218, 11 bits
        unsigned uy = __float2uint_rn(wy * 4096.f); if (uy > 4095u) uy = 4095u;
        unsigned ux = __float2uint_rn(wx * 4096.f); if (ux > 4095u) ux = 4095u;
        int ia = __float2int_rn(affv[m] * 262144.f);
        unsigned long long v =
              ((unsigned long long)((unsigned)ia & 0x1FFFFFu) << 43)
            | ((unsigned long long)ux << 31)
            | ((unsigned long long)uy << 19)
            | ((unsigned long long)xq << 8)
            | (unsigned long long)yq;
        g_tab[(b*8 + slot)*HW + pi] = v;
    }
}

// Fused: 3x3 conv (8ch -> 24ch, f32x2 over a 2-pixel pair) + post + init feat.
__global__ void __launch_bounds__(256) conv_post_kernel(
    const float* __restrict__ feat_init,
    const float* __restrict__ guidance,
    const float* __restrict__ confidence,
    const float* __restrict__ feat_fix,
    const float* __restrict__ w_oa,
    const float* __restrict__ b_oa,
    const float* __restrict__ ascale,
    float* __restrict__ out)
{
    __shared__ unsigned long long wsh2[1728];   // (w,w) pairs, layout [c][dy][dx][o]
    for (int j = threadIdx.x; j < 1728; j += 256){
        int o = j % 24, r = j / 24;
        float w = __ldg(w_oa + o*72 + r);
        wsh2[j] = pack2f(w, w);
    }
    __syncthreads();

    int t  = blockIdx.x*256 + threadIdx.x;
    int pp = t*2;
    int b  = pp / HW;
    int p  = pp - b*HW;
    int y  = p / Ww;
    int x  = p - y*Ww;                 // pixels (x, x+1), x even

    unsigned long long accp[24];
    #pragma unroll
    for (int o=0;o<24;o++){ float bo = __ldg(b_oa+o); accp[o] = pack2f(bo, bo); }

    const float* gb = guidance + (size_t)b*8*HW;
    #pragma unroll 1
    for (int c=0;c<8;c++){
        #pragma unroll
        for (int dy=0;dy<3;dy++){
            int yy = y + dy - 1;
            if ((unsigned)yy >= Hh) continue;
            const float* grow = gb + c*HW + yy*Ww;
            float gva[4];
            gva[0] = (x >= 1)     ? __ldg(grow + x - 1) : 0.f;
            gva[1] =                __ldg(grow + x);
            gva[2] =                __ldg(grow + x + 1);
            gva[3] = (x + 2 < Ww) ? __ldg(grow + x + 2) : 0.f;
            #pragma unroll
            for (int dx=0;dx<3;dx++){
                unsigned long long ga = pack2f(gva[dx], gva[dx+1]);
                const ulonglong2* wp = (const ulonglong2*)(wsh2 + (c*9 + dy*3 + dx)*24);
                #pragma unroll
                for (int q=0;q<12;q++){
                    ulonglong2 w2 = wp[q];
                    asm("fma.rn.f32x2 %0, %1, %2, %0;" : "+l"(accp[2*q])   : "l"(ga), "l"(w2.x));
                    asm("fma.rn.f32x2 %0, %1, %2, %0;" : "+l"(accp[2*q+1]) : "l"(ga), "l"(w2.y));
                }
            }
        }
    }

    float acc0[24], acc1[24];
    #pragma unroll
    for (int o=0;o<24;o++){ float2 u = unpack2f(accp[o]); acc0[o]=u.x; acc1[o]=u.y; }

    const float* cb  = confidence + (size_t)b*HW;
    const float* fxb = feat_fix   + (size_t)b*HW;
    const float* fib = feat_init  + (size_t)b*HW;
    float iasc = 1.0f / (__ldg(ascale) + 1e-8f);

    float* out_off = out + (size_t)Bb*HW;
    float* out_aff = out + (size_t)Bb*HW*19;

    post_pixel(acc0, b, y, x,   cb, iasc, out_off, out_aff);
    post_pixel(acc1, b, y, x+1, cb, iasc, out_off, out_aff);

    // pre-blended initial feat into scalar padded buffer
    float fv0 = __ldg(fxb + p),     fi0 = __ldg(fib + p);
    float fv1 = __ldg(fxb + p + 1), fi1 = __ldg(fib + p + 1);
    float f0 = (fv0 > 0.f) ? fv0 : fi0;
    float f1 = (fv1 > 0.f) ? fv1 : fi1;
    float* pa = g_fa + (size_t)b*PHW2 + (y+8)*PW2 + (x+8);
    pa[0] = f0;
    pa[1] = f1;
}

// One propagation iteration. Block = 4x64 tile; scalar feat window in smem
// (4.6KB -> 8 blocks/SM). 8 explicit taps + implicit center tap with
// aff_ref = 2^18 - sum(iaf) reconstructed in fixed point.
__global__ void __launch_bounds__(256) prop_kernel(
    const float* __restrict__ feat_fix, float* __restrict__ dout, int it)
{
    __shared__ float sf[SROWS*SCOLS];   // 15 x 76 floats = 4560 B

    int bid = blockIdx.x;
    int tid = threadIdx.x;
    int b   = bid / BLK_PER_B;
    int r   = bid - b*BLK_PER_B;
    int yt  = (r / 19) * TH;
    int xs  = (r - (r/19)*19) * TW;

    const float* fin = ((it & 1) ? g_fb : g_fa) + (size_t)b*PHW2;

    // Stage feat window: padded rows [yt+3, yt+17], cols [xs+2, xs+77].
    // Source is 8B-aligned -> float2 staging (570 jobs).
    {
        const float* src = fin + (yt+3)*PW2 + (xs+2);
        #pragma unroll
        for (int pass=0; pass<3; pass++){
            int j = pass*256 + tid;
            if (j < SROWS*38){
                int rr = j / 38, cc = j - rr*38;
                float2 v2 = *reinterpret_cast<const float2*>(src + rr*PW2 + cc*2);
                sf[rr*SCOLS + cc*2]     = v2.x;
                sf[rr*SCOLS + cc*2 + 1] = v2.y;
            }
        }
        __syncthreads();
    }

    int dy = tid >> 6, dx = tid & 63;
    int y  = yt + dy, x = xs + dx;
    int p  = y*Ww + x;
    // padded tap coords are (yq+6, xq+6); window origin is (yt+3, xs+2):
    //   sr = yq - (yt-3)   -> ybase = yt-3
    //   sc = xq - (xs-4)   -> xbase = xs-4
    int ybase = yt - 3;
    int xbase = xs - 4;
    int sioff = ybase*SCOLS + xbase;         // si = yq*76 + xq - sioff

    float acc = 0.f;
    float isum = 0.f;                        // sum of iaf (exact integers)
    #pragma unroll
    for (int k=0;k<8;k++){
        unsigned long long v = __ldg(&g_tab[(b*8 + k)*HW + p]);
        unsigned lo  = (unsigned)v;
        unsigned t8  = lo >> 8;                 // wy field + xq live in low word
        unsigned t20 = (unsigned)(v >> 20);     // 64-bit shift: wx spans bits 31..42
        // mantissa-injection decode: w = (1.0 | frac_bits) - 1.0
        float wy = __uint_as_float(0x3F800000u | (t8  & 0x7FF800u)) - 1.0f;
        float wx = __uint_as_float(0x3F800000u | (t20 & 0x7FF800u)) - 1.0f;
        int yq = (int)(lo & 0xFFu);
        int xq = (int)(t8 & 0x7FFu);
        float iaf = (float)(int)((long long)v >> 43);   // aff * 2^18
        isum += iaf;

        float v00, v01, v10, v11;
        if ((unsigned)(yq - ybase) <= 13u && (unsigned)(xq - xbase) <= 74u){
            int si = yq*SCOLS + xq - sioff;
            v00 = sf[si];
            v01 = sf[si + 1];
            v10 = sf[si + SCOLS];
            v11 = sf[si + SCOLS + 1];
        } else {
            // rare out-of-window tap: exact global fallback (always in-bounds)
            const float* g = fin + (yq + 6)*PW2 + (xq + 6);
            v00 = __ldg(g);
            v01 = __ldg(g + 1);
            v10 = __ldg(g + PW2);
            v11 = __ldg(g + PW2 + 1);
        }
        float top = v00 + wx*(v01 - v00);
        float bot = v10 + wx*(v11 - v10);
        acc = fmaf(iaf, top + wy*(bot - top), acc);
    }
    // implicit center tap: weight aff_ref = 1 - sum(aff), sample = feat[y][x]
    float fown = sf[(y - yt + 5)*SCOLS + (x - xs + 6)];
    acc = fmaf(262144.f - isum, fown, acc);
    acc *= (1.f/262144.f);   // deferred aff fixed-point scale

    int tg = b*HW + p;
    if (it != 17){
        float fv = __ldg(feat_fix + tg);
        float f  = (fv > 0.f) ? fv : acc;
        float* fout = ((it & 1) ? g_fa : g_fb) + (size_t)b*PHW2;
        fout[(y+8)*PW2 + (x+8)] = f;
    } else {
        dout[tg] = acc;                       // final: raw aggregate
    }
}

extern "C" void kernel_launch(void* const* d_in, const int* in_sizes, int n_in,
                              void* d_out, int out_size)
{
    const float* feat_init  = (const float*)d_in[0];
    const float* guidance   = (const float*)d_in[1];
    const float* confidence = (const float*)d_in[2];
    const float* feat_fix   = (const float*)d_in[3];
    const float* w_oa       = (const float*)d_in[4];
    const float* b_oa       = (const float*)d_in[5];
    const float* ascale     = (const float*)d_in[6];
    float* out = (float*)d_out;

    (void)in_sizes; (void)n_in; (void)out_size;

    conv_post_kernel<<<(Bb*HW/2)/256, 256>>>(feat_init, guidance, confidence,
                                             feat_fix, w_oa, b_oa, ascale, out);
    for (int it = 0; it < 18; ++it)
        prop_kernel<<<Bb*BLK_PER_B, 256>>>(feat_fix, out, it);
}

// round 16
// speedup vs baseline: 1.1728x; 1.0007x over previous
#include <cuda_runtime.h>
#include <math.h>

#define Hh 240
#define Ww 1216
#define Bb 4
#define HW (Hh*Ww)
// scalar padded feat buffers, 8-px halo
#define PH2 256
#define PW2 1232
#define PHW2 (PH2*PW2)
// prop tiling: 4 rows x 64 cols per 256-thread block
#define TH 4
#define TW 64
#define SROWS 15
#define SCOLS 76
#define BLK_PER_B 1140   // (240/4)*(1216/64)

// Tap table: one u64 per (pixel, tap), tap-major, 8 taps (center tap m=4 is
// implicit: zero offset, weight aff_ref = 1 - sum(others)):
//   bits [0:8)   y0+2  (0..242)
//   bits [8:19)  x0+2  (0..1218)
//   bits [19:31) wy unorm12 (x/4096), [31:43) wx unorm12 (x/4096)
//   bits [43:64) aff, signed fixed-point 2^-18
__device__ unsigned long long g_tab[Bb*8*HW];
// Scalar padded ping-pong feat buffers. Zero-initialized; 8-px border never
// written -> clamped taps read exact zeros.
__device__ float g_fa[Bb*PHW2];
__device__ float g_fb[Bb*PHW2];

__device__ __forceinline__ unsigned long long pack2f(float a, float b){
    float2 t = make_float2(a, b);
    return *reinterpret_cast<unsigned long long*>(&t);
}
__device__ __forceinline__ float2 unpack2f(unsigned long long v){
    return *reinterpret_cast<float2*>(&v);
}

// Exact-formula fast tanh: tanh(x) = 1 - 2/(e^{2x}+1), via MUFU ex2 + rcp.
// Abs error ~1e-6 (22-bit MUFU); correct limits at +/-inf.
__device__ __forceinline__ float fast_tanh(float x){
    float t, r;
    asm("ex2.approx.f32 %0, %1;" : "=f"(t) : "f"(x * 2.8853900817779268f));
    asm("rcp.approx.f32 %0, %1;" : "=f"(r) : "f"(t + 1.0f));
    return fmaf(-2.0f, r, 1.0f);
}

__device__ __forceinline__ float bilin_conf(const float* __restrict__ img, float sy, float sx)
{
    float fy = floorf(sy), fx = floorf(sx);
    float wy = sy - fy,  wx = sx - fx;
    int y0 = (int)fy, x0 = (int)fx;
    int y1 = y0 + 1, x1 = x0 + 1;
    float v00=0.f, v01=0.f, v10=0.f, v11=0.f;
    bool by0 = (unsigned)y0 < Hh, by1 = (unsigned)y1 < Hh;
    bool bx0 = (unsigned)x0 < Ww, bx1 = (unsigned)x1 < Ww;
    if (by0 && bx0) v00 = __ldg(img + y0*Ww + x0);
    if (by0 && bx1) v01 = __ldg(img + y0*Ww + x1);
    if (by1 && bx0) v10 = __ldg(img + y1*Ww + x0);
    if (by1 && bx1) v11 = __ldg(img + y1*Ww + x1);
    return (1.f-wy)*((1.f-wx)*v00 + wx*v01) + wy*((1.f-wx)*v10 + wx*v11);
}

__device__ __forceinline__ void post_pixel(const float acc[24], int b, int y, int xi,
    const float* __restrict__ cb, float iasc,
    float* __restrict__ out_off, float* __restrict__ out_aff)
{
    int pi = y*Ww + xi;

    float offy[9], offx[9];
    #pragma unroll
    for (int m=0;m<9;m++){
        offy[m] = (m<4) ? acc[2*m]   : ((m==4) ? 0.f : acc[2*(m-1)]);
        offx[m] = (m<4) ? acc[2*m+1] : ((m==4) ? 0.f : acc[2*(m-1)+1]);
    }

    float a8[8], ssum = 0.f;
    #pragma unroll
    for (int k=0;k<8;k++){
        float av = fast_tanh(acc[16+k]) * iasc;
        av *= bilin_conf(cb, (float)y + acc[2*k], (float)xi + acc[2*k+1]);
        a8[k] = av;
        ssum += fabsf(av);
    }
    float s = ssum + 1e-4f;
    if (s < 1.f) s = 1.f;
    float inv = 1.0f / s;
    float asum = 0.f;
    #pragma unroll
    for (int k=0;k<8;k++){ a8[k] *= inv; asum += a8[k]; }
    float aref = 1.f - asum;

    float affv[9];
    #pragma unroll
    for (int m=0;m<9;m++) affv[m] = (m<4) ? a8[m] : ((m==4) ? aref : a8[m-1]);

    // plain stores (measured: __stcs here cost +70us)
    #pragma unroll
    for (int m=0;m<9;m++){
        out_off[((size_t)b*18 + 2*m    )*HW + pi] = offy[m];
        out_off[((size_t)b*18 + 2*m + 1)*HW + pi] = offx[m];
        out_aff[((size_t)b*9  + m      )*HW + pi] = affv[m];
    }

    // encode tap table: 8 entries, center tap (m=4) implicit in prop
    #pragma unroll
    for (int m=0;m<9;m++){
        if (m == 4) continue;
        int slot = (m < 4) ? m : m - 1;
        float ty = (float)(y  + m/3 - 1) + offy[m];
        float tx = (float)(xi + m%3 - 1) + offx[m];
        float fy = floorf(ty), fx2 = floorf(tx);
        float wy = ty - fy, wx = tx - fx2;
        int y0 = (int)fy, x0 = (int)fx2;
        if (y0 < -2) y0 = -2;  if (y0 > Hh) y0 = Hh;   // clamp keeps invalidity
        if (x0 < -2) x0 = -2;  if (x0 > Ww) x0 = Ww;
        unsigned yq = (unsigned)(y0 + 2);              // 0..242, 8 bits
        unsigned xq = (unsigned)(x0 + 2);              // 0..1218, 11 bits
        unsigned uy = __float2uint_rn(wy * 4096.f); if (uy > 4095u) uy = 4095u;
        unsigned ux = __float2uint_rn(wx * 4096.f); if (ux > 4095u) ux = 4095u;
        int ia = __float2int_rn(affv[m] * 262144.f);
        unsigned long long v =
              ((unsigned long long)((unsigned)ia & 0x1FFFFFu) << 43)
            | ((unsigned long long)ux << 31)
            | ((unsigned long long)uy << 19)
            | ((unsigned long long)xq << 8)
            | (unsigned long long)yq;
        g_tab[(b*8 + slot)*HW + pi] = v;
    }
}

// Fused: 3x3 conv (8ch -> 24ch, f32x2 over a 2-pixel pair) + post + init feat.
__global__ void __launch_bounds__(256) conv_post_kernel(
    const float* __restrict__ feat_init,
    const float* __restrict__ guidance,
    const float* __restrict__ confidence,
    const float* __restrict__ feat_fix,
    const float* __restrict__ w_oa,
    const float* __restrict__ b_oa,
    const float* __restrict__ ascale,
    float* __restrict__ out)
{
    __shared__ unsigned long long wsh2[1728];   // (w,w) pairs, layout [c][dy][dx][o]
    for (int j = threadIdx.x; j < 1728; j += 256){
        int o = j % 24, r = j / 24;
        float w = __ldg(w_oa + o*72 + r);
        wsh2[j] = pack2f(w, w);
    }
    __syncthreads();

    int t  = blockIdx.x*256 + threadIdx.x;
    int pp = t*2;
    int b  = pp / HW;
    int p  = pp - b*HW;
    int y  = p / Ww;
    int x  = p - y*Ww;                 // pixels (x, x+1), x even

    unsigned long long accp[24];
    #pragma unroll
    for (int o=0;o<24;o++){ float bo = __ldg(b_oa+o); accp[o] = pack2f(bo, bo); }

    const float* gb = guidance + (size_t)b*8*HW;
    #pragma unroll 1
    for (int c=0;c<8;c++){
        #pragma unroll
        for (int dy=0;dy<3;dy++){
            int yy = y + dy - 1;
            if ((unsigned)yy >= Hh) continue;
            const float* grow = gb + c*HW + yy*Ww;
            float gva[4];
            gva[0] = (x >= 1)     ? __ldg(grow + x - 1) : 0.f;
            gva[1] =                __ldg(grow + x);
            gva[2] =                __ldg(grow + x + 1);
            gva[3] = (x + 2 < Ww) ? __ldg(grow + x + 2) : 0.f;
            #pragma unroll
            for (int dx=0;dx<3;dx++){
                unsigned long long ga = pack2f(gva[dx], gva[dx+1]);
                const ulonglong2* wp = (const ulonglong2*)(wsh2 + (c*9 + dy*3 + dx)*24);
                #pragma unroll
                for (int q=0;q<12;q++){
                    ulonglong2 w2 = wp[q];
                    asm("fma.rn.f32x2 %0, %1, %2, %0;" : "+l"(accp[2*q])   : "l"(ga), "l"(w2.x));
                    asm("fma.rn.f32x2 %0, %1, %2, %0;" : "+l"(accp[2*q+1]) : "l"(ga), "l"(w2.y));
                }
            }
        }
    }

    float acc0[24], acc1[24];
    #pragma unroll
    for (int o=0;o<24;o++){ float2 u = unpack2f(accp[o]); acc0[o]=u.x; acc1[o]=u.y; }

    const float* cb  = confidence + (size_t)b*HW;
    const float* fxb = feat_fix   + (size_t)b*HW;
    const float* fib = feat_init  + (size_t)b*HW;
    float iasc = 1.0f / (__ldg(ascale) + 1e-8f);

    float* out_off = out + (size_t)Bb*HW;
    float* out_aff = out + (size_t)Bb*HW*19;

    post_pixel(acc0, b, y, x,   cb, iasc, out_off, out_aff);
    post_pixel(acc1, b, y, x+1, cb, iasc, out_off, out_aff);

    // pre-blended initial feat into scalar padded buffer
    float fv0 = __ldg(fxb + p),     fi0 = __ldg(fib + p);
    float fv1 = __ldg(fxb + p + 1), fi1 = __ldg(fib + p + 1);
    float f0 = (fv0 > 0.f) ? fv0 : fi0;
    float f1 = (fv1 > 0.f) ? fv1 : fi1;
    float* pa = g_fa + (size_t)b*PHW2 + (y+8)*PW2 + (x+8);
    pa[0] = f0;
    pa[1] = f1;
}

// One propagation iteration. Block = 4x64 tile; scalar feat window in smem
// (4.6KB -> 8 blocks/SM). 8 explicit taps + implicit center tap with
// aff_ref = 2^18 - sum(iaf) reconstructed in fixed point.
__global__ void __launch_bounds__(256) prop_kernel(
    const float* __restrict__ feat_fix, float* __restrict__ dout, int it)
{
    __shared__ float sf[SROWS*SCOLS];   // 15 x 76 floats = 4560 B

    int bid = blockIdx.x;
    int tid = threadIdx.x;
    int b   = bid / BLK_PER_B;
    int r   = bid - b*BLK_PER_B;
    int yt  = (r / 19) * TH;
    int xs  = (r - (r/19)*19) * TW;

    const float* fin = ((it & 1) ? g_fb : g_fa) + (size_t)b*PHW2;

    // Stage feat window: padded rows [yt+3, yt+17], cols [xs+2, xs+77].
    // Source is 8B-aligned -> float2 staging (570 jobs).
    {
        const float* src = fin + (yt+3)*PW2 + (xs+2);
        #pragma unroll
        for (int pass=0; pass<3; pass++){
            int j = pass*256 + tid;
            if (j < SROWS*38){
                int rr = j / 38, cc = j - rr*38;
                float2 v2 = *reinterpret_cast<const float2*>(src + rr*PW2 + cc*2);
                sf[rr*SCOLS + cc*2]     = v2.x;
                sf[rr*SCOLS + cc*2 + 1] = v2.y;
            }
        }
        __syncthreads();
    }

    int dy = tid >> 6, dx = tid & 63;
    int y  = yt + dy, x = xs + dx;
    int p  = y*Ww + x;
    // padded tap coords are (yq+6, xq+6); window origin is (yt+3, xs+2):
    //   sr = yq - (yt-3)   -> ybase = yt-3
    //   sc = xq - (xs-4)   -> xbase = xs-4
    int ybase = yt - 3;
    int xbase = xs - 4;
    int sioff = ybase*SCOLS + xbase;         // si = yq*76 + xq - sioff

    float acc = 0.f;
    float isum = 0.f;                        // sum of iaf (exact integers)
    #pragma unroll
    for (int k=0;k<8;k++){
        unsigned long long v = __ldg(&g_tab[(b*8 + k)*HW + p]);
        unsigned lo  = (unsigned)v;
        unsigned t8  = lo >> 8;                 // wy field + xq live in low word
        unsigned t20 = (unsigned)(v >> 20);     // 64-bit shift: wx spans bits 31..42
        // mantissa-injection decode: w = (1.0 | frac_bits) - 1.0
        float wy = __uint_as_float(0x3F800000u | (t8  & 0x7FF800u)) - 1.0f;
        float wx = __uint_as_float(0x3F800000u | (t20 & 0x7FF800u)) - 1.0f;
        int yq = (int)(lo & 0xFFu);
        int xq = (int)(t8 & 0x7FFu);
        float iaf = (float)(int)((long long)v >> 43);   // aff * 2^18
        isum += iaf;

        float v00, v01, v10, v11;
        if ((unsigned)(yq - ybase) <= 13u && (unsigned)(xq - xbase) <= 74u){
            int si = yq*SCOLS + xq - sioff;
            v00 = sf[si];
            v01 = sf[si + 1];
            v10 = sf[si + SCOLS];
            v11 = sf[si + SCOLS + 1];
        } else {
            // rare out-of-window tap: exact global fallback (always in-bounds)
            const float* g = fin + (yq + 6)*PW2 + (xq + 6);
            v00 = __ldg(g);
            v01 = __ldg(g + 1);
            v10 = __ldg(g + PW2);
            v11 = __ldg(g + PW2 + 1);
        }
        float top = v00 + wx*(v01 - v00);
        float bot = v10 + wx*(v11 - v10);
        acc = fmaf(iaf, top + wy*(bot - top), acc);
    }
    // implicit center tap: weight aff_ref = 1 - sum(aff), sample = feat[y][x]
    float fown = sf[(y - yt + 5)*SCOLS + (x - xs + 6)];
    acc = fmaf(262144.f - isum, fown, acc);
    acc *= (1.f/262144.f);   // deferred aff fixed-point scale

    int tg = b*HW + p;
    if (it != 17){
        float fv = __ldg(feat_fix + tg);
        float f  = (fv > 0.f) ? fv : acc;
        float* fout = ((it & 1) ? g_fa : g_fb) + (size_t)b*PHW2;
        fout[(y+8)*PW2 + (x+8)] = f;
    } else {
        dout[tg] = acc;                       // final: raw aggregate
    }
}

extern "C" void kernel_launch(void* const* d_in, const int* in_sizes, int n_in,
                              void* d_out, int out_size)
{
    const float* feat_init  = (const float*)d_in[0];
    const float* guidance   = (const float*)d_in[1];
    const float* confidence = (const float*)d_in[2];
    const float* feat_fix   = (const float*)d_in[3];
    const float* w_oa       = (const float*)d_in[4];
    const float* b_oa       = (const float*)d_in[5];
    const float* ascale     = (const float*)d_in[6];
    float* out = (float*)d_out;

    (void)in_sizes; (void)n_in; (void)out_size;

    conv_post_kernel<<<(Bb*HW/2)/256, 256>>>(feat_init, guidance, confidence,
                                             feat_fix, w_oa, b_oa, ascale, out);
    for (int it = 0; it < 18; ++it)
        prop_kernel<<<Bb*BLK_PER_B, 256>>>(feat_fix, out, it);
}